// round 10
// baseline (speedup 1.0000x reference)
#include <cuda_runtime.h>
#include <math_constants.h>

#define BB 256
#define SS 4096
#define HH 128
#define SPLIT 4
#define ROWS_PER_CTA (SS / SPLIT)    // 1024
#define NWARP 8
#define NTHREADS (NWARP * 32)        // 256
#define ROWS_PER_ITER (NWARP * 2)    // 16 rows per CTA iteration
#define ITERS (ROWS_PER_CTA / ROWS_PER_ITER) // 64

// Scratch for split partials: per (batch, split): [L, ctx[128], pad]
__device__ float g_partial[BB * SPLIT * (HH + 2)];
__device__ int   g_count[BB];   // zero-initialized; reset by last CTA each launch

// Hardware tanh approximation (MUFU.TANH): 1 MUFU op per element.
__device__ __forceinline__ float tanh_hw(float x) {
    float y;
    asm("tanh.approx.f32 %0, %1;" : "=f"(y) : "f"(x));
    return y;
}

__global__ __launch_bounds__(NTHREADS, 7)   // 36-reg budget, 7 CTAs/SM >= grid/SM
void attn_fused(const float* __restrict__ x, const float* __restrict__ w,
                float* __restrict__ out) {
    const int blk   = blockIdx.x;
    const int batch = blk / SPLIT;
    const int split = blk % SPLIT;
    const int warp  = threadIdx.x >> 5;
    const int lane  = threadIdx.x & 31;

    const float4 w4 = __ldg(reinterpret_cast<const float4*>(w) + lane);

    // this warp's row stream: rows warp*2, warp*2+1, stepping by ROWS_PER_ITER
    const float4* base0 = reinterpret_cast<const float4*>(
        x + (size_t)batch * SS * HH + (size_t)split * ROWS_PER_CTA * HH
          + (size_t)(warp * 2) * HH) + lane;
    const float4* base1 = base0 + (HH / 4);          // next row
    const int step = ROWS_PER_ITER * (HH / 4);       // float4 stride per iteration

    float l = 0.0f;
    float accx = 0.0f, accy = 0.0f, accz = 0.0f, accw = 0.0f;

    // software pipeline: prefetch iteration i+1 before processing iteration i
    float4 a0 = __ldcs(base0);
    float4 a1 = __ldcs(base1);

    #pragma unroll 4
    for (int i = 0; i < ITERS; ++i) {
        float4 b0, b1;
        if (i + 1 < ITERS) {
            b0 = __ldcs(base0 + (size_t)(i + 1) * step);
            b1 = __ldcs(base1 + (size_t)(i + 1) * step);
        }

        float p0 = tanh_hw(a0.x) * w4.x;
        float p1 = tanh_hw(a1.x) * w4.x;
        p0 = fmaf(tanh_hw(a0.y), w4.y, p0);
        p1 = fmaf(tanh_hw(a1.y), w4.y, p1);
        p0 = fmaf(tanh_hw(a0.z), w4.z, p0);
        p1 = fmaf(tanh_hw(a1.z), w4.z, p1);
        p0 = fmaf(tanh_hw(a0.w), w4.w, p0);
        p1 = fmaf(tanh_hw(a1.w), w4.w, p1);

        #pragma unroll
        for (int off = 16; off; off >>= 1) {
            p0 += __shfl_xor_sync(0xffffffffu, p0, off);
            p1 += __shfl_xor_sync(0xffffffffu, p1, off);
        }

        const float e0 = __expf(p0);
        const float e1 = __expf(p1);
        l   += e0 + e1;
        accx = fmaf(e0, a0.x, fmaf(e1, a1.x, accx));
        accy = fmaf(e0, a0.y, fmaf(e1, a1.y, accy));
        accz = fmaf(e0, a0.z, fmaf(e1, a1.z, accz));
        accw = fmaf(e0, a0.w, fmaf(e1, a1.w, accw));

        a0 = b0;
        a1 = b1;
    }

    // ---- CTA combine across 8 warps (plain sums) ----
    __shared__ float sm_l[NWARP];
    __shared__ float4 sm_acc[NWARP][32];

    if (lane == 0) sm_l[warp] = l;
    sm_acc[warp][lane] = make_float4(accx, accy, accz, accw);
    __syncthreads();

    if (threadIdx.x < HH) {
        const int h = threadIdx.x;
        const float* accf = reinterpret_cast<const float*>(sm_acc);
        float L = 0.0f, C = 0.0f;
        #pragma unroll
        for (int ww = 0; ww < NWARP; ++ww) {
            L += sm_l[ww];
            C += accf[ww * HH + h];
        }

        float* o = g_partial + (size_t)blk * (HH + 2);
        if (h == 0) o[0] = L;
        o[1 + h] = C;
    }

    // ---- last CTA of this batch combines the SPLIT partials ----
    __shared__ int s_last;
    __syncthreads();
    if (threadIdx.x == 0) {
        __threadfence();
        const int prev = atomicAdd(&g_count[batch], 1);
        s_last = (prev == SPLIT - 1) ? 1 : 0;
    }
    __syncthreads();

    if (s_last) {
        if (threadIdx.x < HH) {
            const int h = threadIdx.x;
            volatile const float* base =
                g_partial + (size_t)batch * SPLIT * (HH + 2);

            float L = 0.0f, C = 0.0f;
            #pragma unroll
            for (int k = 0; k < SPLIT; ++k) {
                volatile const float* pk = base + (size_t)k * (HH + 2);
                L += pk[0];
                C += pk[1 + h];
            }
            out[(size_t)batch * HH + h] = C / L;
        }
        if (threadIdx.x == 0) g_count[batch] = 0;
    }
}

extern "C" void kernel_launch(void* const* d_in, const int* in_sizes, int n_in,
                              void* d_out, int out_size) {
    const float* x = (const float*)d_in[0];   // [B, S, H] fp32
    const float* w = (const float*)d_in[1];   // [H, 1]    fp32
    float* out = (float*)d_out;               // [B, H]    fp32

    attn_fused<<<BB * SPLIT, NTHREADS>>>(x, w, out);
}

// round 12
// speedup vs baseline: 1.2543x; 1.2543x over previous
#include <cuda_runtime.h>
#include <math_constants.h>
#include <cstdint>

#define BB 256
#define SS 4096
#define HH 128
#define SPLIT 4
#define ROWS_PER_CTA (SS / SPLIT)    // 1024
#define NWARP 8
#define NTHREADS (NWARP * 32)        // 256
#define ROWS_PER_ITER (NWARP * 2)    // 16 rows per CTA iteration
#define ITERS (ROWS_PER_CTA / ROWS_PER_ITER) // 64
#define NSTAGE 3
#define STAGE_BYTES (NWARP * 1024)   // 16 rows * 512B = 8KB per stage

// Scratch for split partials: per (batch, split): [L, ctx[128], pad]
__device__ float g_partial[BB * SPLIT * (HH + 2)];
__device__ int   g_count[BB];   // zero-initialized; reset by last CTA each launch

// Hardware tanh approximation (MUFU.TANH): 1 MUFU op per element.
__device__ __forceinline__ float tanh_hw(float x) {
    float y;
    asm("tanh.approx.f32 %0, %1;" : "=f"(y) : "f"(x));
    return y;
}

__device__ __forceinline__ void cp16(uint32_t dst_smem, const void* src) {
    asm volatile("cp.async.cg.shared.global [%0], [%1], 16;"
                 :: "r"(dst_smem), "l"(src));
}
#define CP_COMMIT() asm volatile("cp.async.commit_group;")
#define CP_WAIT2()  asm volatile("cp.async.wait_group 2;" ::: "memory")

__global__ __launch_bounds__(NTHREADS, 7)
void attn_fused(const float* __restrict__ x, const float* __restrict__ w,
                float* __restrict__ out) {
    // cp.async staging buffer; reused for the combine phase after the loop.
    __shared__ __align__(16) char stage_buf[NSTAGE * STAGE_BYTES];
    __shared__ int s_last;

    const int blk   = blockIdx.x;
    const int batch = blk / SPLIT;
    const int split = blk % SPLIT;
    const int warp  = threadIdx.x >> 5;
    const int lane  = threadIdx.x & 31;

    const float4 w4 = __ldg(reinterpret_cast<const float4*>(w) + lane);

    // this warp's row pair stream (rows warp*2, warp*2+1, stepping 16/iter)
    const float* g0 = x + (size_t)batch * SS * HH + (size_t)split * ROWS_PER_CTA * HH
                        + (size_t)(warp * 2) * HH + lane * 4;
    const float* g1 = g0 + HH;

    // each lane stages (and later consumes) exactly its own two 16B chunks
    uint32_t sb;
    asm("{ .reg .u64 t; cvta.to.shared.u64 t, %1; cvt.u32.u64 %0, t; }"
        : "=r"(sb) : "l"(stage_buf));
    const uint32_t my0 = sb + warp * 1024 + lane * 16;

    // prologue: stages 0,1 in flight
    #pragma unroll
    for (int s = 0; s < NSTAGE - 1; ++s) {
        const uint32_t d = my0 + s * STAGE_BYTES;
        cp16(d,       g0 + (size_t)s * (ROWS_PER_ITER * HH));
        cp16(d + 512, g1 + (size_t)s * (ROWS_PER_ITER * HH));
        CP_COMMIT();
    }

    float l = 0.0f;
    float accx = 0.0f, accy = 0.0f, accz = 0.0f, accw = 0.0f;

    const float4* stage_f4 = reinterpret_cast<const float4*>(stage_buf);
    const int myidx = warp * 64 + lane;   // float4 index of chunk0 within a stage

    #pragma unroll 4
    for (int i = 0; i < ITERS; ++i) {
        // keep the pipeline full: stage i+2
        const int nxt = i + NSTAGE - 1;
        if (nxt < ITERS) {
            const uint32_t d = my0 + (nxt % NSTAGE) * STAGE_BYTES;
            cp16(d,       g0 + (size_t)nxt * (ROWS_PER_ITER * HH));
            cp16(d + 512, g1 + (size_t)nxt * (ROWS_PER_ITER * HH));
        }
        CP_COMMIT();
        CP_WAIT2();   // stage i complete (own data -> no barrier needed)

        const int sbase = (i % NSTAGE) * (STAGE_BYTES / 16);
        const float4 v0 = stage_f4[sbase + myidx];
        const float4 v1 = stage_f4[sbase + myidx + 32];

        float p0 = tanh_hw(v0.x) * w4.x;
        float p1 = tanh_hw(v1.x) * w4.x;
        p0 = fmaf(tanh_hw(v0.y), w4.y, p0);
        p1 = fmaf(tanh_hw(v1.y), w4.y, p1);
        p0 = fmaf(tanh_hw(v0.z), w4.z, p0);
        p1 = fmaf(tanh_hw(v1.z), w4.z, p1);
        p0 = fmaf(tanh_hw(v0.w), w4.w, p0);
        p1 = fmaf(tanh_hw(v1.w), w4.w, p1);

        #pragma unroll
        for (int off = 16; off; off >>= 1) {
            p0 += __shfl_xor_sync(0xffffffffu, p0, off);
            p1 += __shfl_xor_sync(0xffffffffu, p1, off);
        }

        const float e0 = __expf(p0);
        const float e1 = __expf(p1);
        l   += e0 + e1;
        accx = fmaf(e0, v0.x, fmaf(e1, v1.x, accx));
        accy = fmaf(e0, v0.y, fmaf(e1, v1.y, accy));
        accz = fmaf(e0, v0.z, fmaf(e1, v1.z, accz));
        accw = fmaf(e0, v0.w, fmaf(e1, v1.w, accw));
    }

    // ---- CTA combine across 8 warps (reuse stage_buf; fence first) ----
    __syncthreads();
    float*  sm_l   = reinterpret_cast<float*>(stage_buf);           // 8 floats
    float4* sm_acc = reinterpret_cast<float4*>(stage_buf + 128);    // 8*32 float4

    if (lane == 0) sm_l[warp] = l;
    sm_acc[warp * 32 + lane] = make_float4(accx, accy, accz, accw);
    __syncthreads();

    if (threadIdx.x < HH) {
        const int h = threadIdx.x;
        const float* accf = reinterpret_cast<const float*>(sm_acc);
        float L = 0.0f, C = 0.0f;
        #pragma unroll
        for (int ww = 0; ww < NWARP; ++ww) {
            L += sm_l[ww];
            C += accf[ww * HH + h];
        }

        float* o = g_partial + (size_t)blk * (HH + 2);
        if (h == 0) o[0] = L;
        o[1 + h] = C;
    }

    // ---- last CTA of this batch combines the SPLIT partials ----
    __syncthreads();
    if (threadIdx.x == 0) {
        __threadfence();
        const int prev = atomicAdd(&g_count[batch], 1);
        s_last = (prev == SPLIT - 1) ? 1 : 0;
    }
    __syncthreads();

    if (s_last) {
        if (threadIdx.x < HH) {
            const int h = threadIdx.x;
            volatile const float* base =
                g_partial + (size_t)batch * SPLIT * (HH + 2);

            float L = 0.0f, C = 0.0f;
            #pragma unroll
            for (int k = 0; k < SPLIT; ++k) {
                volatile const float* pk = base + (size_t)k * (HH + 2);
                L += pk[0];
                C += pk[1 + h];
            }
            out[(size_t)batch * HH + h] = C / L;
        }
        if (threadIdx.x == 0) g_count[batch] = 0;
    }
}

extern "C" void kernel_launch(void* const* d_in, const int* in_sizes, int n_in,
                              void* d_out, int out_size) {
    const float* x = (const float*)d_in[0];   // [B, S, H] fp32
    const float* w = (const float*)d_in[1];   // [H, 1]    fp32
    float* out = (float*)d_out;               // [B, H]    fp32

    attn_fused<<<BB * SPLIT, NTHREADS>>>(x, w, out);
}

// round 13
// speedup vs baseline: 1.3117x; 1.0457x over previous
#include <cuda_runtime.h>
#include <math_constants.h>

#define BB 256
#define SS 4096
#define HH 128
#define SPLIT 4
#define ROWS_PER_CTA (SS / SPLIT)    // 1024
#define NWARP 8
#define NTHREADS (NWARP * 32)        // 256
#define ROWS_PER_ITER (NWARP * 2)    // 16 rows per CTA iteration
#define ITERS (ROWS_PER_CTA / ROWS_PER_ITER) // 64
#define STEP_F4 (ROWS_PER_ITER * HH / 4)     // 512 float4 per iteration

// Scratch for split partials: per (batch, split): [L, ctx[128], pad]
__device__ float g_partial[BB * SPLIT * (HH + 2)];
__device__ int   g_count[BB];   // zero-initialized; reset by last CTA each launch

// Hardware tanh approximation (MUFU.TANH): 1 MUFU op per element.
__device__ __forceinline__ float tanh_hw(float x) {
    float y;
    asm("tanh.approx.f32 %0, %1;" : "=f"(y) : "f"(x));
    return y;
}

__global__ __launch_bounds__(NTHREADS, 7)
void attn_fused(const float* __restrict__ x, const float* __restrict__ w,
                float* __restrict__ out) {
    const int batch = blockIdx.y;          // 2D grid: no div/mod
    const int split = blockIdx.x;
    const int warp  = threadIdx.x >> 5;
    const int lane  = threadIdx.x & 31;

    const float4 w4 = __ldg(reinterpret_cast<const float4*>(w) + lane);

    // single float4 base pointer; all loop offsets are small 32-bit ints
    const float4* __restrict__ p = reinterpret_cast<const float4*>(
        x + (size_t)batch * (SS * HH) + (size_t)split * (ROWS_PER_CTA * HH))
        + (warp * 2) * (HH / 4) + lane;
    // row0 chunk at p[idx], row1 chunk at p[idx + 32]

    float l = 0.0f;
    float accx = 0.0f, accy = 0.0f, accz = 0.0f, accw = 0.0f;

    // rotate-style software pipeline: cur pair + next pair, peeled last iter
    float4 c0 = __ldcs(p);
    float4 c1 = __ldcs(p + 32);
    int idx = STEP_F4;

    #pragma unroll 4
    for (int i = 0; i < ITERS - 1; ++i) {
        const float4 n0 = __ldcs(p + idx);
        const float4 n1 = __ldcs(p + idx + 32);
        idx += STEP_F4;

        float p0 = tanh_hw(c0.x) * w4.x;
        float p1 = tanh_hw(c1.x) * w4.x;
        p0 = fmaf(tanh_hw(c0.y), w4.y, p0);
        p1 = fmaf(tanh_hw(c1.y), w4.y, p1);
        p0 = fmaf(tanh_hw(c0.z), w4.z, p0);
        p1 = fmaf(tanh_hw(c1.z), w4.z, p1);
        p0 = fmaf(tanh_hw(c0.w), w4.w, p0);
        p1 = fmaf(tanh_hw(c1.w), w4.w, p1);

        #pragma unroll
        for (int off = 16; off; off >>= 1) {
            p0 += __shfl_xor_sync(0xffffffffu, p0, off);
            p1 += __shfl_xor_sync(0xffffffffu, p1, off);
        }

        const float e0 = __expf(p0);
        const float e1 = __expf(p1);
        l   += e0 + e1;
        accx = fmaf(e0, c0.x, fmaf(e1, c1.x, accx));
        accy = fmaf(e0, c0.y, fmaf(e1, c1.y, accy));
        accz = fmaf(e0, c0.z, fmaf(e1, c1.z, accz));
        accw = fmaf(e0, c0.w, fmaf(e1, c1.w, accw));

        c0 = n0;
        c1 = n1;
    }

    // peeled final iteration (no prefetch)
    {
        float p0 = tanh_hw(c0.x) * w4.x;
        float p1 = tanh_hw(c1.x) * w4.x;
        p0 = fmaf(tanh_hw(c0.y), w4.y, p0);
        p1 = fmaf(tanh_hw(c1.y), w4.y, p1);
        p0 = fmaf(tanh_hw(c0.z), w4.z, p0);
        p1 = fmaf(tanh_hw(c1.z), w4.z, p1);
        p0 = fmaf(tanh_hw(c0.w), w4.w, p0);
        p1 = fmaf(tanh_hw(c1.w), w4.w, p1);

        #pragma unroll
        for (int off = 16; off; off >>= 1) {
            p0 += __shfl_xor_sync(0xffffffffu, p0, off);
            p1 += __shfl_xor_sync(0xffffffffu, p1, off);
        }

        const float e0 = __expf(p0);
        const float e1 = __expf(p1);
        l   += e0 + e1;
        accx = fmaf(e0, c0.x, fmaf(e1, c1.x, accx));
        accy = fmaf(e0, c0.y, fmaf(e1, c1.y, accy));
        accz = fmaf(e0, c0.z, fmaf(e1, c1.z, accz));
        accw = fmaf(e0, c0.w, fmaf(e1, c1.w, accw));
    }

    // ---- CTA combine across 8 warps (plain sums) ----
    __shared__ float sm_l[NWARP];
    __shared__ float4 sm_acc[NWARP][32];

    if (lane == 0) sm_l[warp] = l;
    sm_acc[warp][lane] = make_float4(accx, accy, accz, accw);
    __syncthreads();

    const int blk = batch * SPLIT + split;
    if (threadIdx.x < HH) {
        const int h = threadIdx.x;
        const float* accf = reinterpret_cast<const float*>(sm_acc);
        float L = 0.0f, C = 0.0f;
        #pragma unroll
        for (int ww = 0; ww < NWARP; ++ww) {
            L += sm_l[ww];
            C += accf[ww * HH + h];
        }

        float* o = g_partial + (size_t)blk * (HH + 2);
        if (h == 0) o[0] = L;
        o[1 + h] = C;
    }

    // ---- last CTA of this batch combines the SPLIT partials ----
    __shared__ int s_last;
    __syncthreads();
    if (threadIdx.x == 0) {
        __threadfence();
        const int prev = atomicAdd(&g_count[batch], 1);
        s_last = (prev == SPLIT - 1) ? 1 : 0;
    }
    __syncthreads();

    if (s_last) {
        if (threadIdx.x < HH) {
            const int h = threadIdx.x;
            volatile const float* base =
                g_partial + (size_t)batch * SPLIT * (HH + 2);

            float L = 0.0f, C = 0.0f;
            #pragma unroll
            for (int k = 0; k < SPLIT; ++k) {
                volatile const float* pk = base + (size_t)k * (HH + 2);
                L += pk[0];
                C += pk[1 + h];
            }
            out[(size_t)batch * HH + h] = C / L;
        }
        if (threadIdx.x == 0) g_count[batch] = 0;
    }
}

extern "C" void kernel_launch(void* const* d_in, const int* in_sizes, int n_in,
                              void* d_out, int out_size) {
    const float* x = (const float*)d_in[0];   // [B, S, H] fp32
    const float* w = (const float*)d_in[1];   // [H, 1]    fp32
    float* out = (float*)d_out;               // [B, H]    fp32

    dim3 grid(SPLIT, BB);
    attn_fused<<<grid, NTHREADS>>>(x, w, out);
}